// round 7
// baseline (speedup 1.0000x reference)
#include <cuda_runtime.h>
#include <cuda_bf16.h>

#define N_NODES 50000
#define N_EDGES 800000
#define D_IN    96
#define D_EDGE  32
#define D_OUT   96
#define D_FEAT  128          // D_IN + D_EDGE, matches W's K dimension
#define N_TYPES 4

typedef unsigned long long ull;

#define PACKF2(dst, lo, hi) \
    asm("mov.b64 %0, {%1, %2};" : "=l"(dst) : "f"(lo), "f"(hi))
#define UNPACKF2(lo, hi, src) \
    asm("mov.b64 {%0, %1}, %2;" : "=f"(lo), "=f"(hi) : "l"(src))
// packed dual-FMA: acc.lo += a.lo*b.lo ; acc.hi += a.hi*b.hi
#define FFMA2(acc, a, b) \
    asm("fma.rn.f32x2 %0, %1, %2, %0;" : "+l"(acc) : "l"(a), "l"(b))
// vector global reduction (sm_90+): 16B atomic add
#define REDV4(ptr, v) \
    asm volatile("red.global.add.v4.f32 [%0], {%1, %2, %3, %4};" \
                 :: "l"(ptr), "f"((v).x), "f"((v).y), "f"((v).z), "f"((v).w) \
                 : "memory")

// feat[t][n][0:96]   = sum of x[src] over type-t edges into n
// feat[t][n][96:128] = sum of |ef[src]-ef[dst]| over those edges
// then cnt[t][n] (edge counts as float)
#define FEAT_ELEMS ((size_t)N_TYPES * N_NODES * D_FEAT)
#define CNT_OFFSET FEAT_ELEMS
__device__ float g_scratch[FEAT_ELEMS + (size_t)N_TYPES * N_NODES];

// ---------------------------------------------------------------------------
// Kernel 1: edge scatter with vector atomics.
// Lane l owns feat bytes [16l, 16l+16): lanes 0-23 carry x[src] (one LDG.128),
// lanes 24-31 carry |ef[s]-ef[d]| (two LDG.128). One red.v4 per lane per edge.
// ---------------------------------------------------------------------------
#define SC_BATCH 4

__global__ __launch_bounds__(256) void scatter_kernel(
    const float* __restrict__ x,      // [N, 96]
    const float* __restrict__ ef,     // [N, 32]
    const int*   __restrict__ src,    // [E]
    const int*   __restrict__ dst,    // [E]
    const int*   __restrict__ et)     // [E]
{
    const int lane = threadIdx.x & 31;
    const int gw   = (blockIdx.x * blockDim.x + threadIdx.x) >> 5;
    const int nw   = (gridDim.x * blockDim.x) >> 5;

    float* cnt = g_scratch + CNT_OFFSET;

    for (long e0 = (long)gw * SC_BATCH; e0 < N_EDGES; e0 += (long)nw * SC_BATCH) {
        int  s[SC_BATCH], d[SC_BATCH], t[SC_BATCH];
        bool v[SC_BATCH];
#pragma unroll
        for (int i = 0; i < SC_BATCH; i++) {
            long e = e0 + i;
            v[i] = (e < N_EDGES);
            long ec = v[i] ? e : 0;
            s[i] = __ldg(&src[ec]);
            d[i] = __ldg(&dst[ec]);
            t[i] = __ldg(&et[ec]);
        }
#pragma unroll
        for (int i = 0; i < SC_BATCH; i++) {
            if (!v[i]) continue;
            float4 val;
            if (lane < 24) {
                val = *reinterpret_cast<const float4*>(
                          x + (size_t)s[i] * D_IN + 4 * lane);
            } else {
                const float4 a = *reinterpret_cast<const float4*>(
                          ef + (size_t)s[i] * D_EDGE + 4 * (lane - 24));
                const float4 b = *reinterpret_cast<const float4*>(
                          ef + (size_t)d[i] * D_EDGE + 4 * (lane - 24));
                val = make_float4(fabsf(a.x - b.x), fabsf(a.y - b.y),
                                  fabsf(a.z - b.z), fabsf(a.w - b.w));
            }
            float* row = g_scratch + ((size_t)t[i] * N_NODES + d[i]) * D_FEAT;
            REDV4(row + 4 * lane, val);
            if (lane == 0)
                atomicAdd(&cnt[(size_t)t[i] * N_NODES + d[i]], 1.0f);
        }
    }
}

// ---------------------------------------------------------------------------
// Kernel 2: out[n] = sum_t ( feat[t][n] @ 0.25*W[t] + cnt[t][n]*0.25*b[t] ).
// 384 threads, 96-node tiles (8 nodes/warp = 4 packed pairs), type loop in
// registers, one clean store. smem ~99 KB -> 2 CTAs/SM = 24 warps/SM.
// ---------------------------------------------------------------------------
#define TILE_N    96
#define XT_STRIDE 100                         // 400B rows: 16B-aligned
#define SM_XS   (D_FEAT * XT_STRIDE)          // 12800 floats
#define SM_W    (D_FEAT * D_OUT)              // 12288 floats
#define GEMM_SMEM_BYTES ((SM_XS + SM_W + D_OUT + TILE_N + 8) * 4)
#define GEMM_THREADS 384

__global__ __launch_bounds__(GEMM_THREADS) void gemm_kernel(
    const float* __restrict__ W,      // [4, 128, 96]
    const float* __restrict__ b,      // [4, 96]
    float*       __restrict__ out)    // [N, 96]
{
    extern __shared__ __align__(16) float smem[];
    float (*xs)[XT_STRIDE] = (float(*)[XT_STRIDE])smem;       // [128][100]
    float* Wsm = smem + SM_XS;                                 // [128*96]
    float* bsm = smem + SM_XS + SM_W;                          // [96]
    float* csm = bsm + D_OUT;                                  // [96]

    const int node0 = blockIdx.x * TILE_N;
    const int wid   = threadIdx.x >> 5;
    const int lane  = threadIdx.x & 31;
    const int i0    = wid * 8;                // 8 nodes per warp = 4 pairs

    const float* cnt = g_scratch + CNT_OFFSET;

    ull acc[4][3];
#pragma unroll
    for (int p = 0; p < 4; p++)
        acc[p][0] = acc[p][1] = acc[p][2] = 0ull;

    for (int t = 0; t < N_TYPES; t++) {
        __syncthreads();   // previous type's reads done before refill

        const float* Wt = W + (size_t)t * D_FEAT * D_OUT;
        for (int i = threadIdx.x; i < D_FEAT * D_OUT; i += GEMM_THREADS)
            Wsm[i] = 0.25f * Wt[i];
        if (threadIdx.x < D_OUT)
            bsm[threadIdx.x] = 0.25f * b[t * D_OUT + threadIdx.x];
        if (threadIdx.x >= 128 && threadIdx.x < 128 + TILE_N) {
            int r = threadIdx.x - 128;
            int n = node0 + r;
            csm[r] = (n < N_NODES) ? cnt[(size_t)t * N_NODES + n] : 0.0f;
        }
        // transposed feat tile: coalesced gmem read, strided STS (one-time)
        const float* ft = g_scratch + (size_t)t * N_NODES * D_FEAT;
        for (int i = threadIdx.x; i < TILE_N * D_FEAT; i += GEMM_THREADS) {
            int r = i >> 7, k = i & 127;
            int n = node0 + r;
            xs[k][r] = (n < N_NODES) ? ft[(size_t)n * D_FEAT + k] : 0.0f;
        }
        __syncthreads();

#pragma unroll 8
        for (int k = 0; k < D_FEAT; k++) {
            float w0 = Wsm[k * D_OUT + lane];
            float w1 = Wsm[k * D_OUT + lane + 32];
            float w2 = Wsm[k * D_OUT + lane + 64];
            ull W0, W1, W2;
            PACKF2(W0, w0, w0); PACKF2(W1, w1, w1); PACKF2(W2, w2, w2);
#pragma unroll
            for (int h = 0; h < 2; h++) {
                ulonglong2 xv = *reinterpret_cast<const ulonglong2*>(&xs[k][i0 + 4 * h]);
                FFMA2(acc[2 * h][0],     xv.x, W0);
                FFMA2(acc[2 * h][1],     xv.x, W1);
                FFMA2(acc[2 * h][2],     xv.x, W2);
                FFMA2(acc[2 * h + 1][0], xv.y, W0);
                FFMA2(acc[2 * h + 1][1], xv.y, W1);
                FFMA2(acc[2 * h + 1][2], xv.y, W2);
            }
        }

        // bias: acc[p][c] += pack(cnt_lo, cnt_hi) * pack(b_c, b_c)
        float bb0 = bsm[lane], bb1 = bsm[lane + 32], bb2 = bsm[lane + 64];
        ull B0, B1, B2;
        PACKF2(B0, bb0, bb0); PACKF2(B1, bb1, bb1); PACKF2(B2, bb2, bb2);
#pragma unroll
        for (int p = 0; p < 4; p++) {
            ull CN;
            PACKF2(CN, csm[i0 + 2 * p], csm[i0 + 2 * p + 1]);
            FFMA2(acc[p][0], CN, B0);
            FFMA2(acc[p][1], CN, B1);
            FFMA2(acc[p][2], CN, B2);
        }
    }

#pragma unroll
    for (int p = 0; p < 4; p++) {
        int n_lo = node0 + i0 + 2 * p;
        int n_hi = n_lo + 1;
        float* o_lo = out + (size_t)n_lo * D_OUT;
        float* o_hi = out + (size_t)n_hi * D_OUT;
#pragma unroll
        for (int c = 0; c < 3; c++) {
            float lo, hi;
            UNPACKF2(lo, hi, acc[p][c]);
            if (n_lo < N_NODES) o_lo[lane + 32 * c] = lo;
            if (n_hi < N_NODES) o_hi[lane + 32 * c] = hi;
        }
    }
}

// ---------------------------------------------------------------------------
extern "C" void kernel_launch(void* const* d_in, const int* in_sizes, int n_in,
                              void* d_out, int out_size)
{
    const float* x   = (const float*)d_in[0];          // [N, 96]
    const float* ef  = (const float*)d_in[1];          // [N, 32]
    const int*   ei  = (const int*)  d_in[2];          // [2, E]
    const int*   et  = (const int*)  d_in[3];          // [E]
    const float* W   = (const float*)d_in[4];          // [4, 128, 96]
    const float* b   = (const float*)d_in[5];          // [4, 96]
    float*       out = (float*)d_out;                  // [N, 96]

    const int* srcp = ei;
    const int* dstp = ei + N_EDGES;

    // zero the aggregation scratch (feat + cnt)
    void* scratch_ptr = nullptr;
    cudaGetSymbolAddress(&scratch_ptr, g_scratch);
    cudaMemsetAsync(scratch_ptr, 0, sizeof(g_scratch), 0);

    scatter_kernel<<<592, 256>>>(x, ef, srcp, dstp, et);

    static int smem_set = 0;
    if (!smem_set) {
        cudaFuncSetAttribute(gemm_kernel,
                             cudaFuncAttributeMaxDynamicSharedMemorySize,
                             GEMM_SMEM_BYTES);
        smem_set = 1;
    }
    gemm_kernel<<<(N_NODES + TILE_N - 1) / TILE_N, GEMM_THREADS,
                  GEMM_SMEM_BYTES>>>(W, b, out);
}